// round 14
// baseline (speedup 1.0000x reference)
#include <cuda_runtime.h>
#include <cuda_bf16.h>
#include <cstdint>
#include <cstddef>

#define TSTEPS 512
#define NBATCH 64
#define HID    1024
#define NGATE  4096
#define TBROWS (TSTEPS * NBATCH)          // 32768
#define GH     (NGATE * HID)              // 4194304 = 2^22
#define XLEN   ((size_t)TBROWS * HID)     // 33554432

typedef __nv_bfloat16 bf16;

// lstm_layer dynamic smem: B hi [0,64K), B lo [64K,128K), sGp [128K,+33792)
#define SM_B_HI 0u
#define SM_B_LO 65536u
#define SM_SGP  131072u
#define SM_LSTM_TOTAL 164864
#define SWZ(x) ((x) ^ (((x) >> 3) & 0x30))

// ---------------- static device scratch (no runtime allocation) -------------
__device__ float    g_xw[(size_t)TBROWS * NGATE];     // 536 MB, per-layer reuse
__device__ bf16     g_ahi[XLEN];                      // x splits -> h1 -> h2
__device__ bf16     g_alo[XLEN];
__device__ bf16     g_whi[4ull * GH];                 // wih0, whh0, wih1, whh1
__device__ bf16     g_wlo[4ull * GH];
__device__ float    g_bias[2 * NGATE];
__device__ unsigned g_barcnt;                         // monotonic grid barrier

// ---------------- helpers ---------------------------------------------------
static __device__ __forceinline__ uint32_t sptr(const void* p) {
    return (uint32_t)__cvta_generic_to_shared(p);
}
static __device__ __forceinline__ void ldsm4(uint32_t* r, uint32_t a) {
    asm volatile("ldmatrix.sync.aligned.m8n8.x4.shared.b16 {%0,%1,%2,%3}, [%4];\n"
                 : "=r"(r[0]), "=r"(r[1]), "=r"(r[2]), "=r"(r[3]) : "r"(a));
}
static __device__ __forceinline__ void mma_nt(float* d, const uint32_t* a,
                                              uint32_t b0, uint32_t b1) {
    asm volatile(
        "mma.sync.aligned.m16n8k16.row.col.f32.bf16.bf16.f32 "
        "{%0,%1,%2,%3},{%4,%5,%6,%7},{%8,%9},{%0,%1,%2,%3};\n"
        : "+f"(d[0]), "+f"(d[1]), "+f"(d[2]), "+f"(d[3])
        : "r"(a[0]), "r"(a[1]), "r"(a[2]), "r"(a[3]), "r"(b0), "r"(b1));
}
static __device__ __forceinline__ void cpa16(uint32_t dst, const void* src) {
    asm volatile("cp.async.cg.shared.global [%0], [%1], 16;\n" :: "r"(dst), "l"(src));
}
#define CP_COMMIT() asm volatile("cp.async.commit_group;\n")
#define CP_WAIT0()  asm volatile("cp.async.wait_group 0;\n")

// fast activations via MUFU ex2 path (~2 ulp)
static __device__ __forceinline__ float sigf(float x) {
    return __fdividef(1.f, 1.f + __expf(-x));
}
static __device__ __forceinline__ float tanhf_fast(float x) {
    float e = __expf(-2.f * fabsf(x));
    float t = __fdividef(1.f - e, 1.f + e);
    return copysignf(t, x);
}

// Grid barrier over NCTA CTAs: monotonic ticket counter (graph-replay safe).
template <unsigned NCTA>
static __device__ __forceinline__ void grid_barrier() {
    __syncthreads();
    if (threadIdx.x == 0) {
        __threadfence();
        unsigned tk = atomicAdd(&g_barcnt, 1u);
        unsigned target = (tk / NCTA) * NCTA + NCTA;
        while ((int)(*(volatile unsigned*)&g_barcnt - target) < 0) {}
        __threadfence();
    }
    __syncthreads();
}

// ---------------- prep: fp32 -> bf16 hi/lo splits (x + 4 weights), biases ----
__global__ void prep_split(const float* __restrict__ x,
                           const float* __restrict__ w0, const float* __restrict__ w1,
                           const float* __restrict__ w2, const float* __restrict__ w3,
                           bf16* __restrict__ ahi, bf16* __restrict__ alo,
                           bf16* __restrict__ whi, bf16* __restrict__ wlo) {
    const size_t total = XLEN + 4ull * GH;
    for (size_t i = (size_t)blockIdx.x * blockDim.x + threadIdx.x; i < total;
         i += (size_t)gridDim.x * blockDim.x) {
        float v; bf16 *dh, *dl;
        if (i < XLEN) {
            v = x[i]; dh = ahi + i; dl = alo + i;
        } else {
            size_t j = i - XLEN;
            int w = (int)(j >> 22);
            size_t k = j & (GH - 1);
            const float* src = (w == 0) ? w0 : (w == 1) ? w1 : (w == 2) ? w2 : w3;
            v = src[k]; dh = whi + j; dl = wlo + j;
        }
        bf16 h = __float2bfloat16(v);
        *dh = h;
        *dl = __float2bfloat16(v - __bfloat162float(h));
    }
}
__global__ void prep_bias(const float* __restrict__ a0, const float* __restrict__ b0,
                          const float* __restrict__ a1, const float* __restrict__ b1,
                          float* __restrict__ o) {
    int i = blockIdx.x * blockDim.x + threadIdx.x;
    if (i < NGATE) o[i] = a0[i] + b0[i];
    else if (i < 2 * NGATE) o[i] = a1[i - NGATE] + b1[i - NGATE];
}

// ---------------- big GEMM: out[M,4096] = A[M,1024] @ W[4096,1024]^T + bias --
// (R12 proven config) CTA tile 64x64, BK=32, 2-stage cp.async, ONE sync/iter.
__global__ __launch_bounds__(256) void gemm_xw(
    const bf16* __restrict__ Ahi, const bf16* __restrict__ Alo,
    const bf16* __restrict__ Whi, const bf16* __restrict__ Wlo,
    const float* __restrict__ bias, float* __restrict__ out) {
    __shared__ __align__(16) unsigned char sraw[40960];
    const uint32_t sb = sptr(sraw);

    const int tid = threadIdx.x, warp = tid >> 5, lane = tid & 31;
    const size_t n0 = (size_t)blockIdx.x * 64, m0 = (size_t)blockIdx.y * 64;
    const int lr = tid >> 2, lc = (tid & 3) * 8;

    const bf16* pAhi = Ahi + (m0 + lr) * HID + lc;
    const bf16* pAlo = Alo + (m0 + lr) * HID + lc;
    const bf16* pBhi = Whi + (n0 + lr) * HID + lc;
    const bf16* pBlo = Wlo + (n0 + lr) * HID + lc;
    const uint32_t stb = (uint32_t)((lr * 40 + lc) * 2);

    const int mB = (warp & 3) * 16, nB = (warp >> 2) * 32;
    const int lrow = lane & 15;
    const uint32_t lkb2 = (uint32_t)((lane >> 4) * 16);
    const uint32_t aHiB  = sb +         (uint32_t)((mB + lrow) * 80) + lkb2;
    const uint32_t aLoB  = aHiB + 10240;
    const uint32_t bHiB0 = sb + 20480 + (uint32_t)((nB + lrow) * 80) + lkb2;
    const uint32_t bHiB1 = sb + 20480 + (uint32_t)((nB + 16 + lrow) * 80) + lkb2;
    const uint32_t bLoB0 = bHiB0 + 10240;
    const uint32_t bLoB1 = bHiB1 + 10240;

    float acc[4][4];
#pragma unroll
    for (int i = 0; i < 4; ++i)
#pragma unroll
        for (int j = 0; j < 4; ++j) acc[i][j] = 0.f;

#define GEMM_ISSUE(it, s) do {                                   \
        cpa16(sb +         (s) * 5120 + stb, pAhi + (it) * 32);  \
        cpa16(sb + 10240 + (s) * 5120 + stb, pAlo + (it) * 32);  \
        cpa16(sb + 20480 + (s) * 5120 + stb, pBhi + (it) * 32);  \
        cpa16(sb + 30720 + (s) * 5120 + stb, pBlo + (it) * 32);  \
        CP_COMMIT(); } while (0)

    GEMM_ISSUE(0, 0);
    for (int it = 0; it < 32; ++it) {
        CP_WAIT0();
        __syncthreads();
        if (it < 31) GEMM_ISSUE(it + 1, (it + 1) & 1);
        const uint32_t so = (uint32_t)((it & 1) * 5120);
#pragma unroll
        for (int kk = 0; kk < 2; ++kk) {
            const uint32_t ko = so + kk * 32;
            uint32_t ah[4], al[4], bh0[4], bh1[4], bl0[4], bl1[4];
            ldsm4(ah, aHiB + ko);   ldsm4(al, aLoB + ko);
            ldsm4(bh0, bHiB0 + ko); ldsm4(bh1, bHiB1 + ko);
            ldsm4(bl0, bLoB0 + ko); ldsm4(bl1, bLoB1 + ko);
            mma_nt(acc[0], ah, bh0[0], bh0[2]); mma_nt(acc[0], ah, bl0[0], bl0[2]);
            mma_nt(acc[0], al, bh0[0], bh0[2]);
            mma_nt(acc[1], ah, bh0[1], bh0[3]); mma_nt(acc[1], ah, bl0[1], bl0[3]);
            mma_nt(acc[1], al, bh0[1], bh0[3]);
            mma_nt(acc[2], ah, bh1[0], bh1[2]); mma_nt(acc[2], ah, bl1[0], bl1[2]);
            mma_nt(acc[2], al, bh1[0], bh1[2]);
            mma_nt(acc[3], ah, bh1[1], bh1[3]); mma_nt(acc[3], ah, bl1[1], bl1[3]);
            mma_nt(acc[3], al, bh1[1], bh1[3]);
        }
    }
#undef GEMM_ISSUE
    __syncthreads();

    const size_t row0 = m0 + mB + (lane >> 2);
#pragma unroll
    for (int nb = 0; nb < 4; ++nb) {
        const size_t col = n0 + nB + nb * 8 + (lane & 3) * 2;
        const float b0 = bias[col], b1 = bias[col + 1];
        float2* o0 = (float2*)(out + row0 * NGATE + col);
        float2* o1 = (float2*)(out + (row0 + 8) * NGATE + col);
        *o0 = make_float2(acc[nb][0] + b0, acc[nb][1] + b1);
        *o1 = make_float2(acc[nb][2] + b0, acc[nb][3] + b1);
    }
}

// ---------------- persistent recurrent layer ---------------------------------
// 128 CTAs. CTA: 64 batch x 8 h-cols x 4 gates (N=32), K=1024.
// 8 warps = 4 k-groups x 2 m-halves; warp tile 32m x 32n.
// B (W_hh hi/lo) resident in SMEM with per-tile k-PERMUTED columns so that A
// fragments load as LDG.128 straight from global (no smem staging, NO syncs in
// the k-loop — warps free-run). One syncthreads per step + grid barrier.
// Permutation (within each k32 tile): true col c=8t+d  ->  phys (d>>1)*8+2t+(c&1)
__global__ __launch_bounds__(256) void lstm_layer(
    const bf16* __restrict__ Whi, const bf16* __restrict__ Wlo,   // whh splits
    const float* __restrict__ xw,                                 // [512][64][4096]
    bf16* __restrict__ hHi, bf16* __restrict__ hLo,               // slot t out / t-1 in
    float* __restrict__ outF) {                                   // null for layer 0
    extern __shared__ __align__(16) unsigned char sraw[];
    float* sGp = (float*)(sraw + SM_SGP);      // [4][64][33] fp32
    const uint32_t sb = sptr(sraw);

    const int tid = threadIdx.x, warp = tid >> 5, lane = tid & 31;
    const int hs = blockIdx.x * 8;
    const int kg = warp >> 1;                  // k-group 0..3 (k-tiles 8kg..8kg+7)
    const int mhalf = warp & 1;                // rows mhalf*32 .. +31

    // ---- one-time resident B load with k-permutation (LDG+STS, pairs) ----
    for (int i = tid; i < 32768; i += 256) {
        const int part = i >> 14;              // 0 hi, 1 lo
        const int rem  = i & 16383;
        const int tile = rem >> 9;             // 0..31
        const int rr   = (rem >> 4) & 31;      // n row: gate*8 + hcol
        const int pr   = rem & 15;             // true col pair index
        const int wrow = (rr >> 3) * HID + hs + (rr & 7);
        const uint32_t v = *(const uint32_t*)(((part ? Wlo : Whi)
                            + (size_t)wrow * HID + tile * 32 + pr * 2));
        const uint32_t phys = (uint32_t)((pr & 3) * 8 + (pr >> 2) * 2);
        *(uint32_t*)(sraw + (part ? SM_B_LO : SM_B_HI) + tile * 2048
                     + SWZ((uint32_t)(rr * 64 + phys * 2))) = v;
    }
    __syncthreads();

    // ---- A direct-LDG per-lane addressing ----
    const int g = lane >> 2, t4 = lane & 3;
    const size_t aoff0  = (size_t)(mhalf * 32 + g) * HID + t4 * 8;  // elements
    const size_t aoff16 = aoff0 + 16 * HID;

    // ---- B ldsm bases ----
    const uint32_t b_row0 = (uint32_t)((lane & 15) * 64);
    const uint32_t b_row1 = b_row0 + 16 * 64;
    const uint32_t ac16   = (uint32_t)((lane >> 4) * 16);

    // epilogue element mapping (2 per thread)
    const int em0 = tid >> 3,         ej0 = tid & 7;
    const int em1 = (tid + 256) >> 3, ej1 = (tid + 256) & 7;

    float creg[2] = {0.f, 0.f};
    float xr[2][4];

#define LOAD_XR(tt) do {                                              \
        const float* xwt_ = xw + (size_t)(tt) * NBATCH * NGATE;       \
        const float* p0_ = xwt_ + (size_t)em0 * NGATE + hs + ej0;     \
        const float* p1_ = xwt_ + (size_t)em1 * NGATE + hs + ej1;     \
        xr[0][0] = p0_[0];       xr[0][1] = p0_[HID];                 \
        xr[0][2] = p0_[2 * HID]; xr[0][3] = p0_[3 * HID];             \
        xr[1][0] = p1_[0];       xr[1][1] = p1_[HID];                 \
        xr[1][2] = p1_[2 * HID]; xr[1][3] = p1_[3 * HID];             \
    } while (0)

    LOAD_XR(0);

#pragma unroll 1
    for (int t = 0; t < TSTEPS; ++t) {
        float acc[2][4][4];
#pragma unroll
        for (int a = 0; a < 2; ++a)
#pragma unroll
            for (int b = 0; b < 4; ++b)
#pragma unroll
                for (int q = 0; q < 4; ++q) acc[a][b][q] = 0.f;

        if (t > 0) {
            const bf16* pAh = hHi + (size_t)(t - 1) * NBATCH * HID;
            const bf16* pAl = hLo + (size_t)(t - 1) * NBATCH * HID;

            uint4 aL[2][2][2], aH[2][2][2];   // [buf][msub][part]
#define LOADA(bs, kt) do {                                                \
        const size_t ko_ = (size_t)(kt) * 32;                             \
        aL[bs][0][0] = *(const uint4*)(pAh + aoff0 + ko_);                \
        aH[bs][0][0] = *(const uint4*)(pAh + aoff0 + 8 * HID + ko_);      \
        aL[bs][1][0] = *(const uint4*)(pAh + aoff16 + ko_);               \
        aH[bs][1][0] = *(const uint4*)(pAh + aoff16 + 8 * HID + ko_);     \
        aL[bs][0][1] = *(const uint4*)(pAl + aoff0 + ko_);                \
        aH[bs][0][1] = *(const uint4*)(pAl + aoff0 + 8 * HID + ko_);      \
        aL[bs][1][1] = *(const uint4*)(pAl + aoff16 + ko_);               \
        aH[bs][1][1] = *(const uint4*)(pAl + aoff16 + 8 * HID + ko_);     \
    } while (0)

            LOADA(0, 8 * kg);
#pragma unroll
            for (int r = 0; r < 8; ++r) {
                const int bs = r & 1, ns = bs ^ 1;
                const int kt = 8 * kg + r;
                if (r < 7) LOADA(ns, kt + 1);
                const uint32_t bt = (uint32_t)(kt * 2048);
#pragma unroll
                for (int kk = 0; kk < 2; ++kk) {
                    const uint32_t ca = ac16 + (uint32_t)kk * 32;
                    uint32_t bhA[4], bhB[4], blA[4], blB[4];
                    ldsm4(bhA, sb + SM_B_HI + bt + SWZ(b_row0 + ca));
                    ldsm4(bhB, sb + SM_B_HI + bt + SWZ(b_row1 + ca));
                    ldsm4(blA, sb + SM_B_LO + bt + SWZ(b_row0 + ca));
                    ldsm4(blB, sb + SM_B_LO + bt + SWZ(b_row1 + ca));
#pragma unroll
                    for (int ms = 0; ms < 2; ++ms) {
                        uint32_t fh[4], fl[4];
                        if (kk == 0) {
                            fh[0] = aL[bs][ms][0].x; fh[1] = aH[bs][ms][0].x;
                            fh[2] = aL[bs][ms][0].y; fh[3] = aH[bs][ms][0].y;
                            fl[0] = aL[bs][ms][1].x; fl[1] = aH[bs][ms][1].x;
                            fl[2] = aL[bs][ms][1].y; fl[3] = aH[bs][ms][1].y;
                        } else {
                            fh[0] = aL[bs][ms][0].z; fh[1] = aH[bs][ms][0].z;
                            fh[2] = aL[bs][ms][0].w; fh[3] = aH[bs][ms][0].w;
                            fl[0] = aL[bs][ms][1].z; fl[1] = aH[bs][ms][1].z;
                            fl[2] = aL[bs][ms][1].w; fl[3] = aH[bs][ms][1].w;
                        }
                        mma_nt(acc[ms][0], fh, bhA[0], bhA[2]);
                        mma_nt(acc[ms][0], fh, blA[0], blA[2]);
                        mma_nt(acc[ms][0], fl, bhA[0], bhA[2]);
                        mma_nt(acc[ms][1], fh, bhA[1], bhA[3]);
                        mma_nt(acc[ms][1], fh, blA[1], blA[3]);
                        mma_nt(acc[ms][1], fl, bhA[1], bhA[3]);
                        mma_nt(acc[ms][2], fh, bhB[0], bhB[2]);
                        mma_nt(acc[ms][2], fh, blB[0], blB[2]);
                        mma_nt(acc[ms][2], fl, bhB[0], bhB[2]);
                        mma_nt(acc[ms][3], fh, bhB[1], bhB[3]);
                        mma_nt(acc[ms][3], fh, blB[1], blB[3]);
                        mma_nt(acc[ms][3], fl, bhB[1], bhB[3]);
                    }
                }
            }
#undef LOADA
        }

        // write split-K partials: sGp[kg][row][col], col = gate*8 + hcol
        {
            const int r0 = mhalf * 32 + (lane >> 2);
            const int c0 = (lane & 3) * 2;
#pragma unroll
            for (int mb = 0; mb < 2; ++mb) {
                const int base = kg * 2112 + (r0 + mb * 16) * 33 + c0;
#pragma unroll
                for (int nb = 0; nb < 4; ++nb) {
                    const int idx = base + nb * 8;
                    sGp[idx]              = acc[mb][nb][0];
                    sGp[idx + 1]          = acc[mb][nb][1];
                    sGp[idx + 8 * 33]     = acc[mb][nb][2];
                    sGp[idx + 8 * 33 + 1] = acc[mb][nb][3];
                }
            }
        }
        __syncthreads();

        // epilogue: 64 batch x 8 h-cols = 512 elements; sum 4 k-group partials
        const size_t obase = (size_t)t * NBATCH * HID;
        {
            const int i0 = em0 * 33 + ej0;
            const float ii = sGp[i0] + sGp[i0 + 2112] + sGp[i0 + 4224] + sGp[i0 + 6336] + xr[0][0];
            const int i1 = i0 + 8;
            const float ff = sGp[i1] + sGp[i1 + 2112] + sGp[i1 + 4224] + sGp[i1 + 6336] + xr[0][1];
            const int i2 = i0 + 16;
            const float gg = sGp[i2] + sGp[i2 + 2112] + sGp[i2 + 4224] + sGp[i2 + 6336] + xr[0][2];
            const int i3 = i0 + 24;
            const float oo = sGp[i3] + sGp[i3 + 2112] + sGp[i3 + 4224] + sGp[i3 + 6336] + xr[0][3];
            const float c = sigf(ff) * creg[0] + sigf(ii) * tanhf_fast(gg);
            const float h = sigf(oo) * tanhf_fast(c);
            creg[0] = c;
            const bf16 hh = __float2bfloat16(h);
            const size_t oidx = obase + (size_t)em0 * HID + hs + ej0;
            hHi[oidx] = hh;
            hLo[oidx] = __float2bfloat16(h - __bfloat162float(hh));
            if (outF) outF[oidx] = h;
        }
        {
            const int i0 = em1 * 33 + ej1;
            const float ii = sGp[i0] + sGp[i0 + 2112] + sGp[i0 + 4224] + sGp[i0 + 6336] + xr[1][0];
            const int i1 = i0 + 8;
            const float ff = sGp[i1] + sGp[i1 + 2112] + sGp[i1 + 4224] + sGp[i1 + 6336] + xr[1][1];
            const int i2 = i0 + 16;
            const float gg = sGp[i2] + sGp[i2 + 2112] + sGp[i2 + 4224] + sGp[i2 + 6336] + xr[1][2];
            const int i3 = i0 + 24;
            const float oo = sGp[i3] + sGp[i3 + 2112] + sGp[i3 + 4224] + sGp[i3 + 6336] + xr[1][3];
            const float c = sigf(ff) * creg[1] + sigf(ii) * tanhf_fast(gg);
            const float h = sigf(oo) * tanhf_fast(c);
            creg[1] = c;
            const bf16 hh = __float2bfloat16(h);
            const size_t oidx = obase + (size_t)em1 * HID + hs + ej1;
            hHi[oidx] = hh;
            hLo[oidx] = __float2bfloat16(h - __bfloat162float(hh));
            if (outF) outF[oidx] = h;
        }

        // prefetch next step's xw BEFORE the barrier (overlaps barrier wait)
        if (t + 1 < TSTEPS) LOAD_XR(t + 1);
        grid_barrier<128>();
    }
#undef LOAD_XR
}

// ---------------- host ------------------------------------------------------
extern "C" void kernel_launch(void* const* d_in, const int* in_sizes, int n_in,
                              void* d_out, int out_size) {
    const float* x    = (const float*)d_in[0];
    const float* wih0 = (const float*)d_in[1];
    const float* whh0 = (const float*)d_in[2];
    const float* bih0 = (const float*)d_in[3];
    const float* bhh0 = (const float*)d_in[4];
    const float* wih1 = (const float*)d_in[5];
    const float* whh1 = (const float*)d_in[6];
    const float* bih1 = (const float*)d_in[7];
    const float* bhh1 = (const float*)d_in[8];

    float *xw, *bias;
    bf16 *ahi, *alo, *whi, *wlo;
    cudaGetSymbolAddress((void**)&xw,   g_xw);
    cudaGetSymbolAddress((void**)&ahi,  g_ahi);
    cudaGetSymbolAddress((void**)&alo,  g_alo);
    cudaGetSymbolAddress((void**)&whi,  g_whi);
    cudaGetSymbolAddress((void**)&wlo,  g_wlo);
    cudaGetSymbolAddress((void**)&bias, g_bias);

    cudaFuncSetAttribute(lstm_layer, cudaFuncAttributeMaxDynamicSharedMemorySize,
                         SM_LSTM_TOTAL);

    // launch order fixed so ncu (-s 5 -c 1) profiles lstm_layer (layer 1)
    prep_split<<<4096, 256>>>(x, wih0, whh0, wih1, whh1, ahi, alo, whi, wlo);
    prep_bias<<<32, 256>>>(bih0, bhh0, bih1, bhh1, bias);

    for (int layer = 0; layer < 2; ++layer) {
        const size_t wih_off = (size_t)(2 * layer) * GH;
        const size_t whh_off = (size_t)(2 * layer + 1) * GH;
        gemm_xw<<<dim3(64, 512), 256>>>(ahi, alo, whi + wih_off, wlo + wih_off,
                                        bias + layer * NGATE, xw);
        lstm_layer<<<128, 256, SM_LSTM_TOTAL>>>(whi + whh_off, wlo + whh_off, xw,
                                                ahi, alo,
                                                layer ? (float*)d_out : nullptr);
    }
}